// round 9
// baseline (speedup 1.0000x reference)
#include <cuda_runtime.h>
#include <cstdint>

#define BB   8192
#define TT   128
#define HID  64
#define NTH  128   // thread pair (2k,2k+1) owns hidden unit k
#define GRID (BB / 2)   // 2 sequences per CTA

// Precomputed input-path tables (filled by precompute_tables kernel).
__device__ float gTA[7 * 192];
__device__ float gTAS[20 * 192];
__device__ float gWbet[192];

// Packed fp32x2 FMA: d = a*b + d (FFMA2, only emitted via PTX fma.rn.f32x2)
__device__ __forceinline__ void ffma2(unsigned long long &d,
                                      unsigned long long a,
                                      unsigned long long b) {
    asm("fma.rn.f32x2 %0, %1, %2, %0;" : "+l"(d) : "l"(a), "l"(b));
}
__device__ __forceinline__ float lo32(unsigned long long v) {
    return __uint_as_float((unsigned)v);
}
__device__ __forceinline__ float hi32(unsigned long long v) {
    return __uint_as_float((unsigned)(v >> 32));
}
__device__ __forceinline__ float red2(unsigned long long v) {
    return lo32(v) + hi32(v);
}

__device__ __forceinline__ float sigm_fast(float x) {
    return __fdividef(1.f, 1.f + __expf(-x));
}
__device__ __forceinline__ float tanh_fast(float x) {
    return 1.f - 2.f * __fdividef(1.f, __expf(2.f * x) + 1.f);
}

// One block of 192 threads; thread r computes row r of all tables.
__global__ void precompute_tables(const float* __restrict__ E_actor,   // [7,8]
                                  const float* __restrict__ E_action,  // [4,8]
                                  const float* __restrict__ E_street,  // [5,4]
                                  const float* __restrict__ W_proj,    // [32,21]
                                  const float* __restrict__ b_proj,    // [32]
                                  const float* __restrict__ W_ih,      // [192,32]
                                  const float* __restrict__ b_ih)      // [192]
{
    const int r = threadIdx.x;   // 0..191
    float M[21];
    #pragma unroll
    for (int c = 0; c < 21; c++) {
        float s = 0.f;
        for (int i = 0; i < 32; i++) s += W_ih[r * 32 + i] * W_proj[i * 21 + c];
        M[c] = s;
    }
    float b0 = b_ih[r];
    for (int i = 0; i < 32; i++) b0 += W_ih[r * 32 + i] * b_proj[i];

    for (int a = 0; a < 7; a++) {
        float s = b0;
        #pragma unroll
        for (int c = 0; c < 8; c++) s += M[c] * E_actor[a * 8 + c];
        gTA[a * 192 + r] = s;
    }
    for (int ac = 0; ac < 4; ac++) {
        float sa = 0.f;
        #pragma unroll
        for (int c = 0; c < 8; c++) sa += M[8 + c] * E_action[ac * 8 + c];
        for (int st = 0; st < 5; st++) {
            float s = sa;
            #pragma unroll
            for (int c = 0; c < 4; c++) s += M[16 + c] * E_street[st * 4 + c];
            gTAS[(ac * 5 + st) * 192 + r] = s;
        }
    }
    gWbet[r] = M[20];
}

__global__ __launch_bounds__(NTH, 3)
void gru_seq_kernel(const int*  __restrict__ actor,
                    const int*  __restrict__ action,
                    const int*  __restrict__ street,
                    const float* __restrict__ bet,
                    const int*  __restrict__ mask,            // bool->int32 [B,T]
                    const float* __restrict__ W_hh,           // [192,64]
                    const float* __restrict__ b_hh,           // [192]
                    float* __restrict__ out)                  // [B,64]
{
    __shared__ __align__(16) float TA_s[7 * 192];
    __shared__ __align__(16) float TAS_s[20 * 192];
    __shared__ __align__(16) float wbet_s[192];
    __shared__ __align__(16) float h_s[2][2][HID];  // [seq][buf][unit]
    __shared__ int   aoff_s[2][TT];
    __shared__ int   coff_s[2][TT];
    __shared__ float bet_s[2][TT];

    const int j    = threadIdx.x;
    const int b0   = blockIdx.x * 2;    // first sequence id
    const int b1   = b0 + 1;            // second sequence id
    const int k    = j >> 1;            // hidden unit 0..63
    const int half = j & 1;             // which 32-wide half of the dot
    const int rR = k, rZ = k + 64, rN = k + 128;

    // ---- load tables to shared (vectorized) ----
    {
        const float4* src1 = (const float4*)gTA;
        float4*       dst1 = (float4*)TA_s;
        for (int i = j; i < 7 * 192 / 4; i += NTH) dst1[i] = src1[i];
        const float4* src2 = (const float4*)gTAS;
        float4*       dst2 = (float4*)TAS_s;
        for (int i = j; i < 20 * 192 / 4; i += NTH) dst2[i] = src2[i];
        const float4* src3 = (const float4*)gWbet;
        float4*       dst3 = (float4*)wbet_s;
        for (int i = j; i < 192 / 4; i += NTH) dst3[i] = src3[i];
    }
    if (j < HID) {
        h_s[0][0][j] = 0.f; h_s[0][1][j] = 0.f;
        h_s[1][0][j] = 0.f; h_s[1][1][j] = 0.f;
    }

    // ---- per-thread W_hh half-rows (32 floats = 8 ulonglong2) in registers ----
    ulonglong2 wR[8], wZ[8], wN[8];
    {
        const ulonglong2* pR = (const ulonglong2*)(W_hh + rR * 64 + half * 32);
        const ulonglong2* pZ = (const ulonglong2*)(W_hh + rZ * 64 + half * 32);
        const ulonglong2* pN = (const ulonglong2*)(W_hh + rN * 64 + half * 32);
        #pragma unroll
        for (int i = 0; i < 8; i++) { wR[i] = pR[i]; wZ[i] = pZ[i]; wN[i] = pN[i]; }
    }
    const float bhR = b_hh[rR];
    const float bhZ = b_hh[rZ];
    const float bhN = b_hh[rN];

    // ---- sequence lengths from prefix-valid mask (int32 words) ----
    // (__syncthreads_count also orders the table fills above)
    const int len0 = __syncthreads_count(mask[b0 * TT + j] != 0);
    const int len1 = __syncthreads_count(mask[b1 * TT + j] != 0);

    const float wbR = wbet_s[rR];
    const float wbZ = wbet_s[rZ];
    const float wbN = wbet_s[rN];

    // ---- stage per-step table offsets + bet (j covers all TT slots) ----
    aoff_s[0][j] = actor[b0 * TT + j] * 192;
    coff_s[0][j] = (action[b0 * TT + j] * 5 + street[b0 * TT + j]) * 192;
    bet_s[0][j]  = bet[b0 * TT + j];
    aoff_s[1][j] = actor[b1 * TT + j] * 192;
    coff_s[1][j] = (action[b1 * TT + j] * 5 + street[b1 * TT + j]) * 192;
    bet_s[1][j]  = bet[b1 * TT + j];
    __syncthreads();

    // ---- recurrent loop: 2 interleaved sequences, one barrier per step ----
    const int maxlen = max(len0, len1);
    for (int t = 0; t < maxlen; t++) {
        const int  rd = t & 1, wr = rd ^ 1;
        const bool a0 = t < len0;
        const bool a1 = t < len1;

        float pR0, pZ0, pN0, pR1, pZ1, pN1;

        if (a0) {   // half-dots, sequence 0
            const ulonglong2* hp = (const ulonglong2*)h_s[0][rd] + half * 8;
            unsigned long long aR0 = 0, aR1 = 0, aZ0 = 0, aZ1 = 0,
                               aN0 = 0, aN1 = 0;
            #pragma unroll
            for (int i = 0; i < 8; i++) {
                const ulonglong2 hv = hp[i];
                ffma2(aR0, wR[i].x, hv.x);
                ffma2(aR1, wR[i].y, hv.y);
                ffma2(aZ0, wZ[i].x, hv.x);
                ffma2(aZ1, wZ[i].y, hv.y);
                ffma2(aN0, wN[i].x, hv.x);
                ffma2(aN1, wN[i].y, hv.y);
            }
            pR0 = red2(aR0) + red2(aR1);
            pZ0 = red2(aZ0) + red2(aZ1);
            pN0 = red2(aN0) + red2(aN1);
            pR0 += __shfl_xor_sync(0xffffffffu, pR0, 1);
            pZ0 += __shfl_xor_sync(0xffffffffu, pZ0, 1);
            pN0 += __shfl_xor_sync(0xffffffffu, pN0, 1);
        }
        if (a1) {   // half-dots, sequence 1 (independent chain)
            const ulonglong2* hp = (const ulonglong2*)h_s[1][rd] + half * 8;
            unsigned long long aR0 = 0, aR1 = 0, aZ0 = 0, aZ1 = 0,
                               aN0 = 0, aN1 = 0;
            #pragma unroll
            for (int i = 0; i < 8; i++) {
                const ulonglong2 hv = hp[i];
                ffma2(aR0, wR[i].x, hv.x);
                ffma2(aR1, wR[i].y, hv.y);
                ffma2(aZ0, wZ[i].x, hv.x);
                ffma2(aZ1, wZ[i].y, hv.y);
                ffma2(aN0, wN[i].x, hv.x);
                ffma2(aN1, wN[i].y, hv.y);
            }
            pR1 = red2(aR0) + red2(aR1);
            pZ1 = red2(aZ0) + red2(aZ1);
            pN1 = red2(aN0) + red2(aN1);
            pR1 += __shfl_xor_sync(0xffffffffu, pR1, 1);
            pZ1 += __shfl_xor_sync(0xffffffffu, pZ1, 1);
            pN1 += __shfl_xor_sync(0xffffffffu, pN1, 1);
        }

        if (a0) {   // gates, sequence 0
            const int   ao = aoff_s[0][t];
            const int   co = coff_s[0][t];
            const float bf = bet_s[0][t];
            const float xgR = TA_s[ao + rR] + TAS_s[co + rR] + wbR * bf;
            const float xgZ = TA_s[ao + rZ] + TAS_s[co + rZ] + wbZ * bf;
            const float xgN = TA_s[ao + rN] + TAS_s[co + rN] + wbN * bf;
            const float r   = sigm_fast(xgR + pR0 + bhR);
            const float z   = sigm_fast(xgZ + pZ0 + bhZ);
            const float n   = tanh_fast(xgN + r * (pN0 + bhN));
            const float hk  = h_s[0][rd][k];
            if (half == 0) h_s[0][wr][k] = (1.f - z) * n + z * hk;
        }
        if (a1) {   // gates, sequence 1
            const int   ao = aoff_s[1][t];
            const int   co = coff_s[1][t];
            const float bf = bet_s[1][t];
            const float xgR = TA_s[ao + rR] + TAS_s[co + rR] + wbR * bf;
            const float xgZ = TA_s[ao + rZ] + TAS_s[co + rZ] + wbZ * bf;
            const float xgN = TA_s[ao + rN] + TAS_s[co + rN] + wbN * bf;
            const float r   = sigm_fast(xgR + pR1 + bhR);
            const float z   = sigm_fast(xgZ + pZ1 + bhZ);
            const float n   = tanh_fast(xgN + r * (pN1 + bhN));
            const float hk  = h_s[1][rd][k];
            if (half == 0) h_s[1][wr][k] = (1.f - z) * n + z * hk;
        }

        __syncthreads();   // write buffers visible before next step reads
    }

    if (j < HID) {
        out[(long long)b0 * HID + j] = h_s[0][len0 & 1][j];
        out[(long long)b1 * HID + j] = h_s[1][len1 & 1][j];
    }
}

extern "C" void kernel_launch(void* const* d_in, const int* in_sizes, int n_in,
                              void* d_out, int out_size) {
    const int*   actor    = (const int*)  d_in[0];
    const int*   action   = (const int*)  d_in[1];
    const int*   street   = (const int*)  d_in[2];
    const float* bet      = (const float*)d_in[3];
    const int*   mask     = (const int*)  d_in[4];
    const float* E_actor  = (const float*)d_in[5];
    const float* E_action = (const float*)d_in[6];
    const float* E_street = (const float*)d_in[7];
    const float* W_proj   = (const float*)d_in[8];
    const float* b_proj   = (const float*)d_in[9];
    const float* W_ih     = (const float*)d_in[10];
    const float* W_hh     = (const float*)d_in[11];
    const float* b_ih     = (const float*)d_in[12];
    const float* b_hh     = (const float*)d_in[13];
    float*       out      = (float*)      d_out;

    precompute_tables<<<1, 192>>>(E_actor, E_action, E_street,
                                  W_proj, b_proj, W_ih, b_ih);
    gru_seq_kernel<<<GRID, NTH>>>(actor, action, street, bet, mask,
                                  W_hh, b_hh, out);
}

// round 10
// speedup vs baseline: 1.1024x; 1.1024x over previous
#include <cuda_runtime.h>
#include <cstdint>

#define BB   8192
#define TT   128
#define HID  64
#define NTH  128   // thread pair (2k,2k+1) owns hidden unit k

// Gate-packed input tables (filled by precompute_tables kernel).
// gTA4[(a*64+k)*4 + g]  : actor contribution for unit k, gate g (R,Z,N,pad),
//                         includes b_ih + W_ih@b_proj, and b_hh folded for R,Z.
// gTAS4[(c*64+k)*4 + g] : action*5+street contribution.
// gWbet[r]              : bet coefficient for gate row r (r = g*64+k).
__device__ float gTA4[7 * 64 * 4];
__device__ float gTAS4[20 * 64 * 4];
__device__ float gWbet[192];

// Packed fp32x2 FMA: d = a*b + d (FFMA2, only emitted via PTX fma.rn.f32x2)
__device__ __forceinline__ void ffma2(unsigned long long &d,
                                      unsigned long long a,
                                      unsigned long long b) {
    asm("fma.rn.f32x2 %0, %1, %2, %0;" : "+l"(d) : "l"(a), "l"(b));
}
__device__ __forceinline__ float lo32(unsigned long long v) {
    return __uint_as_float((unsigned)v);
}
__device__ __forceinline__ float hi32(unsigned long long v) {
    return __uint_as_float((unsigned)(v >> 32));
}
__device__ __forceinline__ float red2(unsigned long long v) {
    return lo32(v) + hi32(v);
}

__device__ __forceinline__ float sigm_fast(float x) {
    return __fdividef(1.f, 1.f + __expf(-x));
}
__device__ __forceinline__ float tanh_fast(float x) {
    return 1.f - 2.f * __fdividef(1.f, __expf(2.f * x) + 1.f);
}

// One block of 192 threads; thread r computes gate row r of all tables.
__global__ void precompute_tables(const float* __restrict__ E_actor,   // [7,8]
                                  const float* __restrict__ E_action,  // [4,8]
                                  const float* __restrict__ E_street,  // [5,4]
                                  const float* __restrict__ W_proj,    // [32,21]
                                  const float* __restrict__ b_proj,    // [32]
                                  const float* __restrict__ W_ih,      // [192,32]
                                  const float* __restrict__ b_ih,      // [192]
                                  const float* __restrict__ b_hh)      // [192]
{
    const int r = threadIdx.x;   // 0..191
    const int k = r & 63;        // hidden unit
    const int g = r >> 6;        // gate 0=R,1=Z,2=N
    float M[21];
    #pragma unroll
    for (int c = 0; c < 21; c++) {
        float s = 0.f;
        for (int i = 0; i < 32; i++) s += W_ih[r * 32 + i] * W_proj[i * 21 + c];
        M[c] = s;
    }
    float b0 = b_ih[r];
    for (int i = 0; i < 32; i++) b0 += W_ih[r * 32 + i] * b_proj[i];
    if (g < 2) b0 += b_hh[r];     // fold recurrent bias for R,Z gates

    for (int a = 0; a < 7; a++) {
        float s = b0;
        #pragma unroll
        for (int c = 0; c < 8; c++) s += M[c] * E_actor[a * 8 + c];
        gTA4[(a * 64 + k) * 4 + g] = s;
    }
    for (int ac = 0; ac < 4; ac++) {
        float sa = 0.f;
        #pragma unroll
        for (int c = 0; c < 8; c++) sa += M[8 + c] * E_action[ac * 8 + c];
        for (int st = 0; st < 5; st++) {
            float s = sa;
            #pragma unroll
            for (int c = 0; c < 4; c++) s += M[16 + c] * E_street[st * 4 + c];
            gTAS4[((ac * 5 + st) * 64 + k) * 4 + g] = s;
        }
    }
    gWbet[r] = M[20];
}

__global__ __launch_bounds__(NTH, 3)
void gru_seq_kernel(const int*  __restrict__ actor,
                    const int*  __restrict__ action,
                    const int*  __restrict__ street,
                    const float* __restrict__ bet,
                    const int*  __restrict__ mask,            // bool->int32 [B,T]
                    const float* __restrict__ W_hh,           // [192,64]
                    const float* __restrict__ b_hh,           // [192]
                    float* __restrict__ out)                  // [B,64]
{
    __shared__ __align__(16) float TA4_s[7 * 64 * 4];    //  7 KB
    __shared__ __align__(16) float TAS4_s[20 * 64 * 4];  // 20 KB
    __shared__ __align__(16) float h_s[2][HID];          // double-buffered hidden
    __shared__ __align__(16) int2  idx_s[TT];            // {aoff4, coff4}
    __shared__ __align__(16) float bet_s[TT];

    const int j    = threadIdx.x;
    const int b    = blockIdx.x;        // sequence id
    const int k    = j >> 1;            // hidden unit 0..63
    const int half = j & 1;             // which 32-wide half of the dot
    const int rR = k, rZ = k + 64, rN = k + 128;

    // ---- load tables to shared (vectorized) ----
    {
        const float4* src1 = (const float4*)gTA4;
        float4*       dst1 = (float4*)TA4_s;
        for (int i = j; i < 7 * 64; i += NTH) dst1[i] = src1[i];
        const float4* src2 = (const float4*)gTAS4;
        float4*       dst2 = (float4*)TAS4_s;
        for (int i = j; i < 20 * 64; i += NTH) dst2[i] = src2[i];
    }
    if (j < HID) { h_s[0][j] = 0.f; h_s[1][j] = 0.f; }

    // ---- per-thread W_hh half-rows (32 floats = 8 ulonglong2) in registers ----
    ulonglong2 wR[8], wZ[8], wN[8];
    {
        const ulonglong2* pR = (const ulonglong2*)(W_hh + rR * 64 + half * 32);
        const ulonglong2* pZ = (const ulonglong2*)(W_hh + rZ * 64 + half * 32);
        const ulonglong2* pN = (const ulonglong2*)(W_hh + rN * 64 + half * 32);
        #pragma unroll
        for (int i = 0; i < 8; i++) { wR[i] = pR[i]; wZ[i] = pZ[i]; wN[i] = pN[i]; }
    }
    const float bhN = b_hh[rN];         // only N's recurrent bias stays separate
    const float wbR = gWbet[rR];
    const float wbZ = gWbet[rZ];
    const float wbN = gWbet[rN];

    // ---- sequence length from prefix-valid mask (int32 words) ----
    // (__syncthreads_count also orders the table fills above)
    const int len = __syncthreads_count(mask[b * TT + j] != 0);

    // ---- stage per-step uniforms: premultiplied float4 offsets + bet ----
    idx_s[j] = make_int2(actor[b * TT + j] * 64,
                         (action[b * TT + j] * 5 + street[b * TT + j]) * 64);
    bet_s[j] = bet[b * TT + j];
    __syncthreads();

    const float4* TA4v  = (const float4*)TA4_s;
    const float4* TAS4v = (const float4*)TAS4_s;

    // xg for t = 0
    float xgR, xgZ, xgN;
    {
        const int2  ic = idx_s[0];
        const float bf = bet_s[0];
        const float4 xa = TA4v[ic.x + k];
        const float4 xc = TAS4v[ic.y + k];
        xgR = xa.x + xc.x + wbR * bf;
        xgZ = xa.y + xc.y + wbZ * bf;
        xgN = xa.z + xc.z + wbN * bf;
    }

    float hk = 0.f;                     // own h[k], kept in register

    // ---- recurrent loop: ONE barrier per step, xg pipelined ----
    for (int t = 0; t < len; t++) {
        const int rd = t & 1, wr = rd ^ 1;
        const ulonglong2* hp = (const ulonglong2*)h_s[rd] + half * 8;

        // half-dots for the three gate rows of unit k (2 chains each)
        unsigned long long aR0 = 0, aR1 = 0, aZ0 = 0, aZ1 = 0, aN0 = 0, aN1 = 0;
        #pragma unroll
        for (int i = 0; i < 8; i++) {
            const ulonglong2 hv = hp[i];
            ffma2(aR0, wR[i].x, hv.x);
            ffma2(aR1, wR[i].y, hv.y);
            ffma2(aZ0, wZ[i].x, hv.x);
            ffma2(aZ1, wZ[i].y, hv.y);
            ffma2(aN0, wN[i].x, hv.x);
            ffma2(aN1, wN[i].y, hv.y);
        }
        float pR = red2(aR0) + red2(aR1);
        float pZ = red2(aZ0) + red2(aZ1);
        float pN = red2(aN0) + red2(aN1);

        // merge the two halves of each dot across the thread pair
        pR += __shfl_xor_sync(0xffffffffu, pR, 1);
        pZ += __shfl_xor_sync(0xffffffffu, pZ, 1);
        pN += __shfl_xor_sync(0xffffffffu, pN, 1);

        // prefetch xg for step t+1 (independent of h; hides under the dots)
        const int tn = (t + 1 < TT) ? t + 1 : TT - 1;
        float nxgR, nxgZ, nxgN;
        {
            const int2  ic = idx_s[tn];
            const float bf = bet_s[tn];
            const float4 xa = TA4v[ic.x + k];
            const float4 xc = TAS4v[ic.y + k];
            nxgR = xa.x + xc.x + wbR * bf;
            nxgZ = xa.y + xc.y + wbZ * bf;
            nxgN = xa.z + xc.z + wbN * bf;
        }

        // gates (biases for R,Z already folded into the tables)
        const float r = sigm_fast(xgR + pR);
        const float z = sigm_fast(xgZ + pZ);
        const float n = tanh_fast(xgN + r * (pN + bhN));
        hk = n + z * (hk - n);
        if (half == 0) h_s[wr][k] = hk;

        xgR = nxgR; xgZ = nxgZ; xgN = nxgN;
        __syncthreads();   // write buffer visible before next step reads
    }

    if (half == 0) out[(long long)b * HID + k] = hk;
}

extern "C" void kernel_launch(void* const* d_in, const int* in_sizes, int n_in,
                              void* d_out, int out_size) {
    const int*   actor    = (const int*)  d_in[0];
    const int*   action   = (const int*)  d_in[1];
    const int*   street   = (const int*)  d_in[2];
    const float* bet      = (const float*)d_in[3];
    const int*   mask     = (const int*)  d_in[4];
    const float* E_actor  = (const float*)d_in[5];
    const float* E_action = (const float*)d_in[6];
    const float* E_street = (const float*)d_in[7];
    const float* W_proj   = (const float*)d_in[8];
    const float* b_proj   = (const float*)d_in[9];
    const float* W_ih     = (const float*)d_in[10];
    const float* W_hh     = (const float*)d_in[11];
    const float* b_ih     = (const float*)d_in[12];
    const float* b_hh     = (const float*)d_in[13];
    float*       out      = (float*)      d_out;

    precompute_tables<<<1, 192>>>(E_actor, E_action, E_street,
                                  W_proj, b_proj, W_ih, b_ih, b_hh);
    gru_seq_kernel<<<BB, NTH>>>(actor, action, street, bet, mask,
                                W_hh, b_hh, out);
}

// round 11
// speedup vs baseline: 1.8431x; 1.6719x over previous
#include <cuda_runtime.h>
#include <cstdint>

#define BB   8192
#define TT   128
#define HID  64
#define NTH  128   // thread pair (2k,2k+1) owns hidden unit k

// Precomputed input-path tables (filled by precompute_tables kernel).
// gTA[a*192+r] includes b_ih + W_ih@b_proj, plus b_hh folded for R,Z rows.
__device__ float gTA[7 * 192];
__device__ float gTAS[20 * 192];
__device__ float gWbet[192];

// Packed fp32x2 FMA: d = a*b + d (FFMA2, only emitted via PTX fma.rn.f32x2)
__device__ __forceinline__ void ffma2(unsigned long long &d,
                                      unsigned long long a,
                                      unsigned long long b) {
    asm("fma.rn.f32x2 %0, %1, %2, %0;" : "+l"(d) : "l"(a), "l"(b));
}
__device__ __forceinline__ float lo32(unsigned long long v) {
    return __uint_as_float((unsigned)v);
}
__device__ __forceinline__ float hi32(unsigned long long v) {
    return __uint_as_float((unsigned)(v >> 32));
}
__device__ __forceinline__ float red2(unsigned long long v) {
    return lo32(v) + hi32(v);
}

__device__ __forceinline__ float sigm_fast(float x) {
    return __fdividef(1.f, 1.f + __expf(-x));
}
__device__ __forceinline__ float tanh_fast(float x) {
    return 1.f - 2.f * __fdividef(1.f, __expf(2.f * x) + 1.f);
}

// One block of 192 threads; thread r computes gate row r of all tables.
__global__ void precompute_tables(const float* __restrict__ E_actor,   // [7,8]
                                  const float* __restrict__ E_action,  // [4,8]
                                  const float* __restrict__ E_street,  // [5,4]
                                  const float* __restrict__ W_proj,    // [32,21]
                                  const float* __restrict__ b_proj,    // [32]
                                  const float* __restrict__ W_ih,      // [192,32]
                                  const float* __restrict__ b_ih,      // [192]
                                  const float* __restrict__ b_hh)      // [192]
{
    const int r = threadIdx.x;   // 0..191
    const int g = r >> 6;        // gate 0=R,1=Z,2=N
    float M[21];
    #pragma unroll
    for (int c = 0; c < 21; c++) {
        float s = 0.f;
        for (int i = 0; i < 32; i++) s += W_ih[r * 32 + i] * W_proj[i * 21 + c];
        M[c] = s;
    }
    float b0 = b_ih[r];
    for (int i = 0; i < 32; i++) b0 += W_ih[r * 32 + i] * b_proj[i];
    if (g < 2) b0 += b_hh[r];    // fold recurrent bias for R,Z gates

    for (int a = 0; a < 7; a++) {
        float s = b0;
        #pragma unroll
        for (int c = 0; c < 8; c++) s += M[c] * E_actor[a * 8 + c];
        gTA[a * 192 + r] = s;
    }
    for (int ac = 0; ac < 4; ac++) {
        float sa = 0.f;
        #pragma unroll
        for (int c = 0; c < 8; c++) sa += M[8 + c] * E_action[ac * 8 + c];
        for (int st = 0; st < 5; st++) {
            float s = sa;
            #pragma unroll
            for (int c = 0; c < 4; c++) s += M[16 + c] * E_street[st * 4 + c];
            gTAS[(ac * 5 + st) * 192 + r] = s;
        }
    }
    gWbet[r] = M[20];
}

__global__ __launch_bounds__(NTH, 4)
void gru_seq_kernel(const int*  __restrict__ actor,
                    const int*  __restrict__ action,
                    const int*  __restrict__ street,
                    const float* __restrict__ bet,
                    const int*  __restrict__ mask,            // bool->int32 [B,T]
                    const float* __restrict__ W_hh,           // [192,64]
                    const float* __restrict__ b_hh,           // [192]
                    float* __restrict__ out)                  // [B,64]
{
    __shared__ __align__(16) float TA_s[7 * 192];
    __shared__ __align__(16) float TAS_s[20 * 192];
    __shared__ __align__(16) float wbet_s[192];
    __shared__ __align__(16) float h_s[2][HID];   // double-buffered hidden
    __shared__ int   aoff_s[TT];
    __shared__ int   coff_s[TT];
    __shared__ float bet_s[TT];

    const int j    = threadIdx.x;
    const int b    = blockIdx.x;        // sequence id
    const int k    = j >> 1;            // hidden unit 0..63
    const int half = j & 1;             // which 32-wide half of the dot
    const int rR = k, rZ = k + 64, rN = k + 128;

    // ---- load tables to shared (vectorized) ----
    {
        const float4* src1 = (const float4*)gTA;
        float4*       dst1 = (float4*)TA_s;
        for (int i = j; i < 7 * 192 / 4; i += NTH) dst1[i] = src1[i];
        const float4* src2 = (const float4*)gTAS;
        float4*       dst2 = (float4*)TAS_s;
        for (int i = j; i < 20 * 192 / 4; i += NTH) dst2[i] = src2[i];
        const float4* src3 = (const float4*)gWbet;
        float4*       dst3 = (float4*)wbet_s;
        for (int i = j; i < 192 / 4; i += NTH) dst3[i] = src3[i];
    }
    if (j < HID) { h_s[0][j] = 0.f; h_s[1][j] = 0.f; }

    // ---- per-thread W_hh half-rows (32 floats = 8 ulonglong2) in registers ----
    ulonglong2 wR[8], wZ[8], wN[8];
    {
        const ulonglong2* pR = (const ulonglong2*)(W_hh + rR * 64 + half * 32);
        const ulonglong2* pZ = (const ulonglong2*)(W_hh + rZ * 64 + half * 32);
        const ulonglong2* pN = (const ulonglong2*)(W_hh + rN * 64 + half * 32);
        #pragma unroll
        for (int i = 0; i < 8; i++) { wR[i] = pR[i]; wZ[i] = pZ[i]; wN[i] = pN[i]; }
    }
    const float bhN = b_hh[rN];         // only N's recurrent bias stays separate

    // ---- sequence length from prefix-valid mask (int32 words) ----
    // (__syncthreads_count also orders the table fills above)
    const int len = __syncthreads_count(mask[b * TT + j] != 0);

    const float wbR = wbet_s[rR];
    const float wbZ = wbet_s[rZ];
    const float wbN = wbet_s[rN];

    // ---- stage per-step table offsets + bet (j covers all TT slots) ----
    aoff_s[j] = actor[b * TT + j] * 192;
    coff_s[j] = (action[b * TT + j] * 5 + street[b * TT + j]) * 192;
    bet_s[j]  = bet[b * TT + j];
    __syncthreads();

    float hk = 0.f;                     // own h[k], register-carried

    // ---- recurrent loop: ONE barrier per step (double-buffered h) ----
    for (int t = 0; t < len; t++) {
        const int rd = t & 1, wr = rd ^ 1;
        const ulonglong2* hp = (const ulonglong2*)h_s[rd] + half * 8;

        // half-dots for the three gate rows of unit k (single chain each)
        unsigned long long aR = 0, aZ = 0, aN = 0;
        #pragma unroll
        for (int i = 0; i < 8; i++) {
            const ulonglong2 hv = hp[i];
            ffma2(aR, wR[i].x, hv.x);
            ffma2(aR, wR[i].y, hv.y);
            ffma2(aZ, wZ[i].x, hv.x);
            ffma2(aZ, wZ[i].y, hv.y);
            ffma2(aN, wN[i].x, hv.x);
            ffma2(aN, wN[i].y, hv.y);
        }
        float pR = red2(aR);
        float pZ = red2(aZ);
        float pN = red2(aN);

        // merge the two halves of each dot across the thread pair
        pR += __shfl_xor_sync(0xffffffffu, pR, 1);
        pZ += __shfl_xor_sync(0xffffffffu, pZ, 1);
        pN += __shfl_xor_sync(0xffffffffu, pN, 1);

        const int   ao = aoff_s[t];
        const int   co = coff_s[t];
        const float bf = bet_s[t];

        const float xgR = TA_s[ao + rR] + TAS_s[co + rR] + wbR * bf;
        const float xgZ = TA_s[ao + rZ] + TAS_s[co + rZ] + wbZ * bf;
        const float xgN = TA_s[ao + rN] + TAS_s[co + rN] + wbN * bf;

        // gates (b_hh for R,Z folded into the tables)
        const float r = sigm_fast(xgR + pR);
        const float z = sigm_fast(xgZ + pZ);
        const float n = tanh_fast(xgN + r * (pN + bhN));
        hk = n + z * (hk - n);
        if (half == 0) h_s[wr][k] = hk;

        __syncthreads();   // write buffer visible before next step reads
    }

    if (half == 0) out[(long long)b * HID + k] = hk;
}

extern "C" void kernel_launch(void* const* d_in, const int* in_sizes, int n_in,
                              void* d_out, int out_size) {
    const int*   actor    = (const int*)  d_in[0];
    const int*   action   = (const int*)  d_in[1];
    const int*   street   = (const int*)  d_in[2];
    const float* bet      = (const float*)d_in[3];
    const int*   mask     = (const int*)  d_in[4];
    const float* E_actor  = (const float*)d_in[5];
    const float* E_action = (const float*)d_in[6];
    const float* E_street = (const float*)d_in[7];
    const float* W_proj   = (const float*)d_in[8];
    const float* b_proj   = (const float*)d_in[9];
    const float* W_ih     = (const float*)d_in[10];
    const float* W_hh     = (const float*)d_in[11];
    const float* b_ih     = (const float*)d_in[12];
    const float* b_hh     = (const float*)d_in[13];
    float*       out      = (float*)      d_out;

    precompute_tables<<<1, 192>>>(E_actor, E_action, E_street,
                                  W_proj, b_proj, W_ih, b_ih, b_hh);
    gru_seq_kernel<<<BB, NTH>>>(actor, action, street, bet, mask,
                                W_hh, b_hh, out);
}

// round 12
// speedup vs baseline: 1.9479x; 1.0568x over previous
#include <cuda_runtime.h>
#include <cstdint>

#define BB   8192
#define TT   128
#define HID  64
#define NTH  128   // thread pair (2k,2k+1) owns hidden unit k

// Precomputed input-path tables (filled by precompute_tables kernel).
// gTA[a*192+r] includes b_ih + W_ih@b_proj, plus b_hh folded for R,Z rows.
__device__ float gTA[7 * 192];
__device__ float gTAS[20 * 192];
__device__ float gWbet[192];

// Packed fp32x2 FMA: d = a*b + d (FFMA2, only emitted via PTX fma.rn.f32x2)
__device__ __forceinline__ void ffma2(unsigned long long &d,
                                      unsigned long long a,
                                      unsigned long long b) {
    asm("fma.rn.f32x2 %0, %1, %2, %0;" : "+l"(d) : "l"(a), "l"(b));
}
__device__ __forceinline__ float lo32(unsigned long long v) {
    return __uint_as_float((unsigned)v);
}
__device__ __forceinline__ float hi32(unsigned long long v) {
    return __uint_as_float((unsigned)(v >> 32));
}
__device__ __forceinline__ float red2(unsigned long long v) {
    return lo32(v) + hi32(v);
}

// Hardware tanh (single MUFU op on sm_75+; 16-cyc latency, rt 8)
__device__ __forceinline__ float tanh_mufu(float x) {
    float y;
    asm("tanh.approx.f32 %0, %1;" : "=f"(y) : "f"(x));
    return y;
}
// sigmoid(x) = 0.5*tanh(x/2) + 0.5  -> one MUFU + one FMA
__device__ __forceinline__ float sigm_mufu(float x) {
    return fmaf(tanh_mufu(0.5f * x), 0.5f, 0.5f);
}

// One block of 192 threads; thread r computes gate row r of all tables.
__global__ void precompute_tables(const float* __restrict__ E_actor,   // [7,8]
                                  const float* __restrict__ E_action,  // [4,8]
                                  const float* __restrict__ E_street,  // [5,4]
                                  const float* __restrict__ W_proj,    // [32,21]
                                  const float* __restrict__ b_proj,    // [32]
                                  const float* __restrict__ W_ih,      // [192,32]
                                  const float* __restrict__ b_ih,      // [192]
                                  const float* __restrict__ b_hh)      // [192]
{
    const int r = threadIdx.x;   // 0..191
    const int g = r >> 6;        // gate 0=R,1=Z,2=N
    float M[21];
    #pragma unroll
    for (int c = 0; c < 21; c++) {
        float s = 0.f;
        for (int i = 0; i < 32; i++) s += W_ih[r * 32 + i] * W_proj[i * 21 + c];
        M[c] = s;
    }
    float b0 = b_ih[r];
    for (int i = 0; i < 32; i++) b0 += W_ih[r * 32 + i] * b_proj[i];
    if (g < 2) b0 += b_hh[r];    // fold recurrent bias for R,Z gates

    for (int a = 0; a < 7; a++) {
        float s = b0;
        #pragma unroll
        for (int c = 0; c < 8; c++) s += M[c] * E_actor[a * 8 + c];
        gTA[a * 192 + r] = s;
    }
    for (int ac = 0; ac < 4; ac++) {
        float sa = 0.f;
        #pragma unroll
        for (int c = 0; c < 8; c++) sa += M[8 + c] * E_action[ac * 8 + c];
        for (int st = 0; st < 5; st++) {
            float s = sa;
            #pragma unroll
            for (int c = 0; c < 4; c++) s += M[16 + c] * E_street[st * 4 + c];
            gTAS[(ac * 5 + st) * 192 + r] = s;
        }
    }
    gWbet[r] = M[20];
}

__global__ __launch_bounds__(NTH, 4)
void gru_seq_kernel(const int*  __restrict__ actor,
                    const int*  __restrict__ action,
                    const int*  __restrict__ street,
                    const float* __restrict__ bet,
                    const int*  __restrict__ mask,            // bool->int32 [B,T]
                    const float* __restrict__ W_hh,           // [192,64]
                    const float* __restrict__ b_hh,           // [192]
                    float* __restrict__ out)                  // [B,64]
{
    __shared__ __align__(16) float TA_s[7 * 192];
    __shared__ __align__(16) float TAS_s[20 * 192];
    __shared__ __align__(16) float wbet_s[192];
    __shared__ __align__(16) float h_s[2][HID];   // double-buffered hidden
    __shared__ int   aoff_s[TT];
    __shared__ int   coff_s[TT];
    __shared__ float bet_s[TT];

    const int j    = threadIdx.x;
    const int b    = blockIdx.x;        // sequence id
    const int k    = j >> 1;            // hidden unit 0..63
    const int half = j & 1;             // which 32-wide half of the dot
    const int rR = k, rZ = k + 64, rN = k + 128;

    // ---- load tables to shared (vectorized) ----
    {
        const float4* src1 = (const float4*)gTA;
        float4*       dst1 = (float4*)TA_s;
        for (int i = j; i < 7 * 192 / 4; i += NTH) dst1[i] = src1[i];
        const float4* src2 = (const float4*)gTAS;
        float4*       dst2 = (float4*)TAS_s;
        for (int i = j; i < 20 * 192 / 4; i += NTH) dst2[i] = src2[i];
        const float4* src3 = (const float4*)gWbet;
        float4*       dst3 = (float4*)wbet_s;
        for (int i = j; i < 192 / 4; i += NTH) dst3[i] = src3[i];
    }
    if (j < HID) { h_s[0][j] = 0.f; h_s[1][j] = 0.f; }

    // ---- per-thread W_hh half-rows (32 floats = 8 ulonglong2) in registers ----
    ulonglong2 wR[8], wZ[8], wN[8];
    {
        const ulonglong2* pR = (const ulonglong2*)(W_hh + rR * 64 + half * 32);
        const ulonglong2* pZ = (const ulonglong2*)(W_hh + rZ * 64 + half * 32);
        const ulonglong2* pN = (const ulonglong2*)(W_hh + rN * 64 + half * 32);
        #pragma unroll
        for (int i = 0; i < 8; i++) { wR[i] = pR[i]; wZ[i] = pZ[i]; wN[i] = pN[i]; }
    }
    const float bhN = b_hh[rN];         // only N's recurrent bias stays separate

    // ---- sequence length from prefix-valid mask (int32 words) ----
    // (__syncthreads_count also orders the table fills above)
    const int len = __syncthreads_count(mask[b * TT + j] != 0);

    const float wbR = wbet_s[rR];
    const float wbZ = wbet_s[rZ];
    const float wbN = wbet_s[rN];

    // ---- stage per-step table offsets + bet (j covers all TT slots) ----
    aoff_s[j] = actor[b * TT + j] * 192;
    coff_s[j] = (action[b * TT + j] * 5 + street[b * TT + j]) * 192;
    bet_s[j]  = bet[b * TT + j];
    __syncthreads();

    float hk = 0.f;                     // own h[k], register-carried

    // ---- recurrent loop: ONE barrier per step (double-buffered h) ----
    for (int t = 0; t < len; t++) {
        const int rd = t & 1, wr = rd ^ 1;
        const ulonglong2* hp = (const ulonglong2*)h_s[rd] + half * 8;

        // half-dots for the three gate rows of unit k (single chain each)
        unsigned long long aR = 0, aZ = 0, aN = 0;
        #pragma unroll
        for (int i = 0; i < 8; i++) {
            const ulonglong2 hv = hp[i];
            ffma2(aR, wR[i].x, hv.x);
            ffma2(aR, wR[i].y, hv.y);
            ffma2(aZ, wZ[i].x, hv.x);
            ffma2(aZ, wZ[i].y, hv.y);
            ffma2(aN, wN[i].x, hv.x);
            ffma2(aN, wN[i].y, hv.y);
        }
        float pR = red2(aR);
        float pZ = red2(aZ);
        float pN = red2(aN);

        // merge the two halves of each dot across the thread pair
        pR += __shfl_xor_sync(0xffffffffu, pR, 1);
        pZ += __shfl_xor_sync(0xffffffffu, pZ, 1);
        pN += __shfl_xor_sync(0xffffffffu, pN, 1);

        const int   ao = aoff_s[t];
        const int   co = coff_s[t];
        const float bf = bet_s[t];

        const float xgR = TA_s[ao + rR] + TAS_s[co + rR] + wbR * bf;
        const float xgZ = TA_s[ao + rZ] + TAS_s[co + rZ] + wbZ * bf;
        const float xgN = TA_s[ao + rN] + TAS_s[co + rN] + wbN * bf;

        // gates via MUFU.TANH (b_hh for R,Z folded into the tables)
        const float r = sigm_mufu(xgR + pR);
        const float z = sigm_mufu(xgZ + pZ);
        const float n = tanh_mufu(xgN + r * (pN + bhN));
        hk = n + z * (hk - n);
        h_s[wr][k] = hk;   // both halves write identical value (post-shfl)

        __syncthreads();   // write buffer visible before next step reads
    }

    if (half == 0) out[(long long)b * HID + k] = hk;
}

extern "C" void kernel_launch(void* const* d_in, const int* in_sizes, int n_in,
                              void* d_out, int out_size) {
    const int*   actor    = (const int*)  d_in[0];
    const int*   action   = (const int*)  d_in[1];
    const int*   street   = (const int*)  d_in[2];
    const float* bet      = (const float*)d_in[3];
    const int*   mask     = (const int*)  d_in[4];
    const float* E_actor  = (const float*)d_in[5];
    const float* E_action = (const float*)d_in[6];
    const float* E_street = (const float*)d_in[7];
    const float* W_proj   = (const float*)d_in[8];
    const float* b_proj   = (const float*)d_in[9];
    const float* W_ih     = (const float*)d_in[10];
    const float* W_hh     = (const float*)d_in[11];
    const float* b_ih     = (const float*)d_in[12];
    const float* b_hh     = (const float*)d_in[13];
    float*       out      = (float*)      d_out;

    precompute_tables<<<1, 192>>>(E_actor, E_action, E_street,
                                  W_proj, b_proj, W_ih, b_ih, b_hh);
    gru_seq_kernel<<<BB, NTH>>>(actor, action, street, bet, mask,
                                W_hh, b_hh, out);
}

// round 13
// speedup vs baseline: 1.9940x; 1.0237x over previous
#include <cuda_runtime.h>
#include <cstdint>

#define BB   8192
#define TT   128
#define HID  64
#define NTH  128   // thread pair (2k,2k+1) owns hidden unit k

// Precomputed input-path tables (filled by precompute_tables kernel).
// gTA[a*192+r] includes b_ih + W_ih@b_proj, plus b_hh folded for R,Z rows.
__device__ float gTA[7 * 192];
__device__ float gTAS[20 * 192];
__device__ float gWbet[192];

// Packed fp32x2 FMA: d = a*b + d (FFMA2, only emitted via PTX fma.rn.f32x2)
__device__ __forceinline__ void ffma2(unsigned long long &d,
                                      unsigned long long a,
                                      unsigned long long b) {
    asm("fma.rn.f32x2 %0, %1, %2, %0;" : "+l"(d) : "l"(a), "l"(b));
}
__device__ __forceinline__ float lo32(unsigned long long v) {
    return __uint_as_float((unsigned)v);
}
__device__ __forceinline__ float hi32(unsigned long long v) {
    return __uint_as_float((unsigned)(v >> 32));
}
__device__ __forceinline__ float red2(unsigned long long v) {
    return lo32(v) + hi32(v);
}

// Hardware tanh (single MUFU op; 16-cyc latency, rt 8)
__device__ __forceinline__ float tanh_mufu(float x) {
    float y;
    asm("tanh.approx.f32 %0, %1;" : "=f"(y) : "f"(x));
    return y;
}
// sigmoid(x) = 0.5*tanh(x/2) + 0.5  -> one MUFU + one FMA
__device__ __forceinline__ float sigm_mufu(float x) {
    return fmaf(tanh_mufu(0.5f * x), 0.5f, 0.5f);
}

// One block of 192 threads; thread r computes gate row r of all tables.
__global__ void precompute_tables(const float* __restrict__ E_actor,   // [7,8]
                                  const float* __restrict__ E_action,  // [4,8]
                                  const float* __restrict__ E_street,  // [5,4]
                                  const float* __restrict__ W_proj,    // [32,21]
                                  const float* __restrict__ b_proj,    // [32]
                                  const float* __restrict__ W_ih,      // [192,32]
                                  const float* __restrict__ b_ih,      // [192]
                                  const float* __restrict__ b_hh)      // [192]
{
    const int r = threadIdx.x;   // 0..191
    const int g = r >> 6;        // gate 0=R,1=Z,2=N
    float M[21];
    #pragma unroll
    for (int c = 0; c < 21; c++) {
        float s = 0.f;
        for (int i = 0; i < 32; i++) s += W_ih[r * 32 + i] * W_proj[i * 21 + c];
        M[c] = s;
    }
    float b0 = b_ih[r];
    for (int i = 0; i < 32; i++) b0 += W_ih[r * 32 + i] * b_proj[i];
    if (g < 2) b0 += b_hh[r];    // fold recurrent bias for R,Z gates

    for (int a = 0; a < 7; a++) {
        float s = b0;
        #pragma unroll
        for (int c = 0; c < 8; c++) s += M[c] * E_actor[a * 8 + c];
        gTA[a * 192 + r] = s;
    }
    for (int ac = 0; ac < 4; ac++) {
        float sa = 0.f;
        #pragma unroll
        for (int c = 0; c < 8; c++) sa += M[8 + c] * E_action[ac * 8 + c];
        for (int st = 0; st < 5; st++) {
            float s = sa;
            #pragma unroll
            for (int c = 0; c < 4; c++) s += M[16 + c] * E_street[st * 4 + c];
            gTAS[(ac * 5 + st) * 192 + r] = s;
        }
    }
    gWbet[r] = M[20];
}

__global__ __launch_bounds__(NTH, 4)
void gru_seq_kernel(const int*  __restrict__ actor,
                    const int*  __restrict__ action,
                    const int*  __restrict__ street,
                    const float* __restrict__ bet,
                    const int*  __restrict__ mask,            // bool->int32 [B,T]
                    const float* __restrict__ W_hh,           // [192,64]
                    const float* __restrict__ b_hh,           // [192]
                    float* __restrict__ out)                  // [B,64]
{
    __shared__ __align__(16) float TA_s[7 * 192];
    __shared__ __align__(16) float TAS_s[20 * 192];
    __shared__ __align__(16) float wbet_s[192];
    __shared__ __align__(16) float h_s[2][HID];   // double-buffered hidden
    __shared__ __align__(16) int4  u_s[TT];       // {aoff, coff, bet_bits, 0}

    const int j    = threadIdx.x;
    const int b    = blockIdx.x;        // sequence id
    const int k    = j >> 1;            // hidden unit 0..63
    const int half = j & 1;             // which 32-wide half of the dot
    const int rR = k, rZ = k + 64, rN = k + 128;
    // this lane's "own" gate row: even -> R, odd -> Z
    const int rMine = half ? rZ : rR;

    // ---- load tables to shared (vectorized) ----
    {
        const float4* src1 = (const float4*)gTA;
        float4*       dst1 = (float4*)TA_s;
        for (int i = j; i < 7 * 192 / 4; i += NTH) dst1[i] = src1[i];
        const float4* src2 = (const float4*)gTAS;
        float4*       dst2 = (float4*)TAS_s;
        for (int i = j; i < 20 * 192 / 4; i += NTH) dst2[i] = src2[i];
        const float4* src3 = (const float4*)gWbet;
        float4*       dst3 = (float4*)wbet_s;
        for (int i = j; i < 192 / 4; i += NTH) dst3[i] = src3[i];
    }
    if (j < HID) { h_s[0][j] = 0.f; h_s[1][j] = 0.f; }

    // ---- per-thread W_hh half-rows (32 floats = 8 ulonglong2) in registers ----
    ulonglong2 wR[8], wZ[8], wN[8];
    {
        const ulonglong2* pR = (const ulonglong2*)(W_hh + rR * 64 + half * 32);
        const ulonglong2* pZ = (const ulonglong2*)(W_hh + rZ * 64 + half * 32);
        const ulonglong2* pN = (const ulonglong2*)(W_hh + rN * 64 + half * 32);
        #pragma unroll
        for (int i = 0; i < 8; i++) { wR[i] = pR[i]; wZ[i] = pZ[i]; wN[i] = pN[i]; }
    }
    const float bhN = b_hh[rN];         // only N's recurrent bias stays separate

    // ---- sequence length from prefix-valid mask (int32 words) ----
    // (__syncthreads_count also orders the table fills above)
    const int len = __syncthreads_count(mask[b * TT + j] != 0);

    const float wbMine = wbet_s[rMine];
    const float wbN    = wbet_s[rN];

    // ---- stage per-step uniforms: one int4 per t ----
    u_s[j] = make_int4(actor[b * TT + j] * 192,
                       (action[b * TT + j] * 5 + street[b * TT + j]) * 192,
                       __float_as_int(bet[b * TT + j]), 0);
    __syncthreads();

    float hk = 0.f;                     // own h[k], register-carried

    // ---- recurrent loop: ONE barrier per step (double-buffered h) ----
    for (int t = 0; t < len; t++) {
        const int rd = t & 1, wr = rd ^ 1;
        const ulonglong2* hp = (const ulonglong2*)h_s[rd] + half * 8;

        // half-dots for the three gate rows of unit k (single chain each)
        unsigned long long aR = 0, aZ = 0, aN = 0;
        #pragma unroll
        for (int i = 0; i < 8; i++) {
            const ulonglong2 hv = hp[i];
            ffma2(aR, wR[i].x, hv.x);
            ffma2(aR, wR[i].y, hv.y);
            ffma2(aZ, wZ[i].x, hv.x);
            ffma2(aZ, wZ[i].y, hv.y);
            ffma2(aN, wN[i].x, hv.x);
            ffma2(aN, wN[i].y, hv.y);
        }
        const float pRh = red2(aR);     // half-sums
        const float pZh = red2(aZ);
        const float pNh = red2(aN);

        // ONE shuffle merges pR for even and pZ for odd:
        // each lane forwards the half-sum the partner needs.
        const float fwd   = half ? pRh : pZh;
        const float got   = __shfl_xor_sync(0xffffffffu, fwd, 1);
        const float pMine = (half ? pZh : pRh) + got;   // full dot of own gate
        // full pN in both lanes
        const float pN = pNh + __shfl_xor_sync(0xffffffffu, pNh, 1);

        // per-step uniforms (single LDS.128, warp-uniform address)
        const int4  uv = u_s[t];
        const float bf = __int_as_float(uv.z);

        // split table loads: even covers R + TA[N]; odd covers Z + TAS[N]
        const float t1 = TA_s[uv.x + rMine];
        const float t2 = TAS_s[uv.y + rMine];
        const float t3 = half ? TAS_s[uv.y + rN] : TA_s[uv.x + rN];

        const float xgMine = t1 + t2 + wbMine * bf;
        const float xgN = t3 + __shfl_xor_sync(0xffffffffu, t3, 1) + wbN * bf;

        // own gate (even: r, odd: z), then swap across the pair
        const float gMine  = sigm_mufu(xgMine + pMine);
        const float gOther = __shfl_xor_sync(0xffffffffu, gMine, 1);
        const float r = half ? gOther : gMine;
        const float z = half ? gMine  : gOther;

        const float n = tanh_mufu(xgN + r * (pN + bhN));
        hk = n + z * (hk - n);
        if (half == 0) h_s[wr][k] = hk;

        __syncthreads();   // write buffer visible before next step reads
    }

    if (half == 0) out[(long long)b * HID + k] = hk;
}

extern "C" void kernel_launch(void* const* d_in, const int* in_sizes, int n_in,
                              void* d_out, int out_size) {
    const int*   actor    = (const int*)  d_in[0];
    const int*   action   = (const int*)  d_in[1];
    const int*   street   = (const int*)  d_in[2];
    const float* bet      = (const float*)d_in[3];
    const int*   mask     = (const int*)  d_in[4];
    const float* E_actor  = (const float*)d_in[5];
    const float* E_action = (const float*)d_in[6];
    const float* E_street = (const float*)d_in[7];
    const float* W_proj   = (const float*)d_in[8];
    const float* b_proj   = (const float*)d_in[9];
    const float* W_ih     = (const float*)d_in[10];
    const float* W_hh     = (const float*)d_in[11];
    const float* b_ih     = (const float*)d_in[12];
    const float* b_hh     = (const float*)d_in[13];
    float*       out      = (float*)      d_out;

    precompute_tables<<<1, 192>>>(E_actor, E_action, E_street,
                                  W_proj, b_proj, W_ih, b_ih, b_hh);
    gru_seq_kernel<<<BB, NTH>>>(actor, action, street, bet, mask,
                                W_hh, b_hh, out);
}